// round 1
// baseline (speedup 1.0000x reference)
#include <cuda_runtime.h>

#define NB 8
#define NT 2048
#define ND 1024
#define NH 64

// Scratch for projected Q/K/V. __device__ globals are zero-initialized, so
// rows that the projection kernel skips (t >= valid_len) read back as 0.0f,
// which is safe for the (masked) attention consumer.
__device__ float g_q[NB * NT * NH];
__device__ float g_k[NB * NT * NH];
__device__ float g_v[NB * NT * NH];

// ---------------------------------------------------------------------------
// Projection kernel: computes q = x@Wq, k = x@Wk, v = x@Wv for one 64-row
// tile of one batch. BM=64, BN=192 (all three mats share the x tile), BK=16.
// Blocks whose entire row range is >= valid_len are skipped (their outputs
// are never read: Q rows >= L are zeroed by the attention kernel, K/V rows
// >= L are masked out).
// ---------------------------------------------------------------------------
__global__ __launch_bounds__(256, 4) void proj_kernel(
    const float* __restrict__ x,
    const float* __restrict__ Wq,
    const float* __restrict__ Wk,
    const float* __restrict__ Wv,
    const int* __restrict__ valid_lens)
{
    const int b  = blockIdx.y;
    const int t0 = blockIdx.x * 64;
    int L = valid_lens[b];
    if (L < 0) L = 0;
    if (L > NT) L = NT;
    if (t0 >= L) return;   // whole tile masked downstream

    __shared__ float xs[16][68];    // [k][row], transposed x tile, padded
    __shared__ float ws[16][196];   // [k][192 cols = Wq|Wk|Wv], padded (196*4 % 16 == 0)

    const int tid = threadIdx.x;
    const int tx  = tid & 15;   // 16 col-groups
    const int ty  = tid >> 4;   // 16 row-groups

    float acc[4][3][4];
    #pragma unroll
    for (int i = 0; i < 4; i++)
        #pragma unroll
        for (int j = 0; j < 3; j++)
            #pragma unroll
            for (int c = 0; c < 4; c++) acc[i][j][c] = 0.f;

    const int r_ld = tid >> 2;         // 0..63
    const int k_ld = (tid & 3) * 4;    // 0,4,8,12

    for (int kb = 0; kb < ND; kb += 16) {
        __syncthreads();
        // x tile 64x16 -> transposed into xs[k][row]
        float4 xv = *(const float4*)&x[((size_t)b * NT + t0 + r_ld) * ND + kb + k_ld];
        xs[k_ld + 0][r_ld] = xv.x;
        xs[k_ld + 1][r_ld] = xv.y;
        xs[k_ld + 2][r_ld] = xv.z;
        xs[k_ld + 3][r_ld] = xv.w;
        // W tiles: 16 x (3*64)
        #pragma unroll
        for (int i = 0; i < 3; i++) {
            int idx4 = tid + 256 * i;          // 0..767 float4s
            int kk   = idx4 / 48;
            int rem  = idx4 % 48;
            int mat  = rem >> 4;
            int h4   = (rem & 15) * 4;
            const float* W = (mat == 0) ? Wq : ((mat == 1) ? Wk : Wv);
            float4 wv = *(const float4*)&W[(size_t)(kb + kk) * NH + h4];
            *(float4*)&ws[kk][mat * 64 + h4] = wv;
        }
        __syncthreads();

        #pragma unroll
        for (int kk = 0; kk < 16; kk++) {
            float4 a  = *(const float4*)&xs[kk][ty * 4];
            float4 b0 = *(const float4*)&ws[kk][tx * 4];
            float4 b1 = *(const float4*)&ws[kk][64 + tx * 4];
            float4 b2 = *(const float4*)&ws[kk][128 + tx * 4];
            float av[4] = {a.x, a.y, a.z, a.w};
            float bv[3][4] = {{b0.x, b0.y, b0.z, b0.w},
                              {b1.x, b1.y, b1.z, b1.w},
                              {b2.x, b2.y, b2.z, b2.w}};
            #pragma unroll
            for (int i = 0; i < 4; i++)
                #pragma unroll
                for (int j = 0; j < 3; j++)
                    #pragma unroll
                    for (int c = 0; c < 4; c++)
                        acc[i][j][c] += av[i] * bv[j][c];
        }
    }

    #pragma unroll
    for (int i = 0; i < 4; i++) {
        size_t base = ((size_t)b * NT + t0 + ty * 4 + i) * NH + tx * 4;
        *(float4*)&g_q[base] = make_float4(acc[i][0][0], acc[i][0][1], acc[i][0][2], acc[i][0][3]);
        *(float4*)&g_k[base] = make_float4(acc[i][1][0], acc[i][1][1], acc[i][1][2], acc[i][1][3]);
        *(float4*)&g_v[base] = make_float4(acc[i][2][0], acc[i][2][1], acc[i][2][2], acc[i][2][3]);
    }
}

// ---------------------------------------------------------------------------
// Flash-attention kernel. 16 query rows per block, 8 threads per row
// (key-split for S = Q K^T, h-split for O += P V). 128 threads/block,
// grid (T/16, B) = 1024 blocks for load balance against the causal triangle.
// ---------------------------------------------------------------------------
__global__ __launch_bounds__(128, 4) void attn_kernel(
    const int* __restrict__ valid_lens, float* __restrict__ out)
{
    const int b  = blockIdx.y;
    const int q0 = blockIdx.x * 16;
    int L = valid_lens[b];
    if (L < 0) L = 0;
    if (L > NT) L = NT;

    const int tid = threadIdx.x;
    const int row = tid >> 3;   // 0..15
    const int t8  = tid & 7;    // 0..7
    const int q   = q0 + row;
    const size_t obase = ((size_t)b * NT + q) * NH;

    if (q0 >= L) {  // whole block masked -> zeros
        float4 z = make_float4(0.f, 0.f, 0.f, 0.f);
        *(float4*)&out[obase + t8 * 4]      = z;
        *(float4*)&out[obase + 32 + t8 * 4] = z;
        return;
    }

    __shared__ float Ks[64][68];
    __shared__ float Vs[64][68];
    __shared__ float Ps[16][72];

    // Q row in registers (replicated across the 8 threads of the row)
    float4 qv[16];
    #pragma unroll
    for (int i = 0; i < 16; i++)
        qv[i] = *(const float4*)&g_q[obase + i * 4];

    float m = -1e30f, l = 0.f;
    float4 o0 = make_float4(0.f, 0.f, 0.f, 0.f);
    float4 o1 = make_float4(0.f, 0.f, 0.f, 0.f);

    const int kend = (q0 + 16 < L) ? (q0 + 16) : L;   // max key index + 1

    for (int j0 = 0; j0 < kend; j0 += 64) {
        __syncthreads();   // previous tile's Vs/Ps fully consumed
        #pragma unroll
        for (int i = 0; i < 8; i++) {
            int idx4 = tid + 128 * i;       // 1024 float4s
            int r    = idx4 >> 4;
            int c4   = (idx4 & 15) * 4;
            size_t g = ((size_t)b * NT + j0 + r) * NH + c4;
            *(float4*)&Ks[r][c4] = *(const float4*)&g_k[g];
            *(float4*)&Vs[r][c4] = *(const float4*)&g_v[g];
        }
        __syncthreads();

        // S: each thread computes 8 strided keys (kk = t8 + 8j)
        float sv[8];
        #pragma unroll
        for (int j = 0; j < 8; j++) {
            const int kk  = t8 + 8 * j;
            const int key = j0 + kk;
            float4 a = make_float4(0.f, 0.f, 0.f, 0.f);
            #pragma unroll
            for (int h4 = 0; h4 < 16; h4++) {
                float4 kvec = *(const float4*)&Ks[kk][h4 * 4];
                a.x += qv[h4].x * kvec.x;
                a.y += qv[h4].y * kvec.y;
                a.z += qv[h4].z * kvec.z;
                a.w += qv[h4].w * kvec.w;
            }
            float s = (a.x + a.y) + (a.z + a.w);
            bool valid = (key <= q) && (key < L);
            sv[j] = valid ? s * 0.125f : -1e30f;
        }

        // tile max across the row's 8 threads (lanes r*8..r*8+7 are contiguous)
        float tm = sv[0];
        #pragma unroll
        for (int j = 1; j < 8; j++) tm = fmaxf(tm, sv[j]);
        #pragma unroll
        for (int off = 1; off < 8; off <<= 1)
            tm = fmaxf(tm, __shfl_xor_sync(0xffffffffu, tm, off));

        const float mn   = fmaxf(m, tm);
        const float corr = __expf(m - mn);   // safe: -1e30 - finite -> expf -> 0

        float psum = 0.f;
        float pj[8];
        #pragma unroll
        for (int j = 0; j < 8; j++) {
            pj[j] = (sv[j] > -1e29f) ? __expf(sv[j] - mn) : 0.f;
            psum += pj[j];
        }
        #pragma unroll
        for (int off = 1; off < 8; off <<= 1)
            psum += __shfl_xor_sync(0xffffffffu, psum, off);

        l = l * corr + psum;
        m = mn;
        o0.x *= corr; o0.y *= corr; o0.z *= corr; o0.w *= corr;
        o1.x *= corr; o1.y *= corr; o1.z *= corr; o1.w *= corr;

        #pragma unroll
        for (int j = 0; j < 8; j++) Ps[row][t8 + 8 * j] = pj[j];
        __syncthreads();

        // O += P V, h split: this thread owns h in [t8*4, t8*4+4) and [32+t8*4, ...)
        #pragma unroll 4
        for (int kk = 0; kk < 64; kk++) {
            const float p = Ps[row][kk];
            float4 v0 = *(const float4*)&Vs[kk][t8 * 4];
            float4 v1 = *(const float4*)&Vs[kk][32 + t8 * 4];
            o0.x += p * v0.x; o0.y += p * v0.y; o0.z += p * v0.z; o0.w += p * v0.w;
            o1.x += p * v1.x; o1.y += p * v1.y; o1.z += p * v1.z; o1.w += p * v1.w;
        }
    }

    const float inv = (q < L && l > 0.f) ? (1.f / l) : 0.f;
    float4 r0 = make_float4(o0.x * inv, o0.y * inv, o0.z * inv, o0.w * inv);
    float4 r1 = make_float4(o1.x * inv, o1.y * inv, o1.z * inv, o1.w * inv);
    *(float4*)&out[obase + t8 * 4]      = r0;
    *(float4*)&out[obase + 32 + t8 * 4] = r1;
}

extern "C" void kernel_launch(void* const* d_in, const int* in_sizes, int n_in,
                              void* d_out, int out_size)
{
    const float* x  = (const float*)d_in[0];
    const float* Wq = (const float*)d_in[1];
    const float* Wk = (const float*)d_in[2];
    const float* Wv = (const float*)d_in[3];
    const int*   vl = (const int*)d_in[4];
    float* out = (float*)d_out;

    proj_kernel<<<dim3(NT / 64, NB), 256>>>(x, Wq, Wk, Wv, vl);
    attn_kernel<<<dim3(NT / 16, NB), 128>>>(vl, out);
}

// round 2
// speedup vs baseline: 1.4313x; 1.4313x over previous
#include <cuda_runtime.h>

#define NB 8
#define NT 2048
#define ND 1024
#define NH 64
#define SPLITS 4
#define NQT (NT / 16)

typedef unsigned long long ull;

// ---------------------------------------------------------------------------
// Packed f32x2 helpers (FFMA2: 2x fp32 throughput, PTX-only on sm_103a)
// ---------------------------------------------------------------------------
__device__ __forceinline__ ull pack2(float lo, float hi) {
    ull r;
    asm("mov.b64 %0, {%1, %2};" : "=l"(r) : "f"(lo), "f"(hi));
    return r;
}
__device__ __forceinline__ ull pack2s(float v) { return pack2(v, v); }
__device__ __forceinline__ void fma2(ull& d, ull a, ull b) {
    asm("fma.rn.f32x2 %0, %1, %2, %0;" : "+l"(d) : "l"(a), "l"(b));
}
__device__ __forceinline__ void mul2(ull& d, ull a) {
    asm("mul.rn.f32x2 %0, %0, %1;" : "+l"(d) : "l"(a));
}
__device__ __forceinline__ float2 unpack2(ull v) {
    float2 r;
    asm("mov.b64 {%0, %1}, %2;" : "=f"(r.x), "=f"(r.y) : "l"(v));
    return r;
}

// Scratch: projected Q/K/V + split-K partials.
__device__ float g_q[NB * NT * NH];
__device__ float g_k[NB * NT * NH];
__device__ float g_v[NB * NT * NH];
__device__ float g_po[NB * NQT * SPLITS * 16 * NH];
__device__ float g_pm[NB * NQT * SPLITS * 16];
__device__ float g_pl[NB * NQT * SPLITS * 16];

// ---------------------------------------------------------------------------
// Projection: one 64x64 output tile of ONE matrix per block (z selects
// Wq/Wk/Wv). BK=16, 256 threads, f32x2 accumulators, reg-prefetch of the
// next global tile overlapping compute. Tiles with t0 >= L are skipped
// (their outputs are never consumed).
// ---------------------------------------------------------------------------
__global__ __launch_bounds__(256) void proj_kernel(
    const float* __restrict__ x,
    const float* __restrict__ Wq,
    const float* __restrict__ Wk,
    const float* __restrict__ Wv,
    const int* __restrict__ valid_lens)
{
    const int b  = blockIdx.y;
    const int t0 = blockIdx.x * 64;
    const int z  = blockIdx.z;
    int L = valid_lens[b];
    if (L < 0) L = 0;
    if (L > NT) L = NT;
    if (t0 >= L) return;

    const float* __restrict__ W = (z == 0) ? Wq : ((z == 1) ? Wk : Wv);
    float* __restrict__ O = (z == 0) ? g_q : ((z == 1) ? g_k : g_v);

    __shared__ __align__(16) float xs[16][72];  // [k][row], stride 72 -> conflict-free STS
    __shared__ __align__(16) float ws[16][68];  // [k][h]

    const int tid = threadIdx.x;
    const int tx  = tid & 15;   // h group (tx*4)
    const int ty  = tid >> 4;   // row group (ty*4)

    const int xr = tid >> 2;          // 0..63 row
    const int xk = (tid & 3) * 4;     // k within tile
    const int wk = tid >> 4;          // 0..15 k
    const int wh = (tid & 15) * 4;    // h

    ull acc[4][2];
    #pragma unroll
    for (int i = 0; i < 4; i++) { acc[i][0] = 0ull; acc[i][1] = 0ull; }

    const float* xp = &x[((size_t)b * NT + t0 + xr) * ND + xk];
    float4 xv = *(const float4*)xp;
    float4 wv = *(const float4*)&W[(size_t)wk * NH + wh];

    for (int kb = 0; kb < ND; kb += 16) {
        __syncthreads();
        xs[xk + 0][xr] = xv.x;
        xs[xk + 1][xr] = xv.y;
        xs[xk + 2][xr] = xv.z;
        xs[xk + 3][xr] = xv.w;
        *(float4*)&ws[wk][wh] = wv;
        if (kb + 16 < ND) {
            xv = *(const float4*)(xp + kb + 16);
            wv = *(const float4*)&W[(size_t)(kb + 16 + wk) * NH + wh];
        }
        __syncthreads();

        #pragma unroll
        for (int kk = 0; kk < 16; kk++) {
            float4 a = *(const float4*)&xs[kk][ty * 4];
            ulonglong2 bv = *(const ulonglong2*)&ws[kk][tx * 4];
            ull a0 = pack2s(a.x), a1 = pack2s(a.y), a2 = pack2s(a.z), a3 = pack2s(a.w);
            fma2(acc[0][0], a0, bv.x); fma2(acc[0][1], a0, bv.y);
            fma2(acc[1][0], a1, bv.x); fma2(acc[1][1], a1, bv.y);
            fma2(acc[2][0], a2, bv.x); fma2(acc[2][1], a2, bv.y);
            fma2(acc[3][0], a3, bv.x); fma2(acc[3][1], a3, bv.y);
        }
    }

    #pragma unroll
    for (int i = 0; i < 4; i++) {
        ulonglong2 st; st.x = acc[i][0]; st.y = acc[i][1];
        *(ulonglong2*)&O[((size_t)b * NT + t0 + ty * 4 + i) * NH + tx * 4] = st;
    }
}

// ---------------------------------------------------------------------------
// Flash-attention partials: 16 q-rows x 8 threads/row, 64-key tiles,
// split-K over SPLITS blocks (z). Writes unnormalized (m, l, o) partials.
// ---------------------------------------------------------------------------
__global__ __launch_bounds__(128) void attn_part(const int* __restrict__ valid_lens)
{
    const int b  = blockIdx.y;
    const int qt = blockIdx.x;
    const int q0 = qt * 16;
    const int s  = blockIdx.z;
    int L = valid_lens[b];
    if (L < 0) L = 0;
    if (L > NT) L = NT;

    const int tid = threadIdx.x;
    const int row = tid >> 3;
    const int t8  = tid & 7;
    const int q   = q0 + row;

    const size_t pidx = (((size_t)b * NQT + qt) * SPLITS + s) * 16 + row;
    float* __restrict__ po = &g_po[pidx * NH];

    const int kend = (q0 + 16 < L) ? (q0 + 16) : L;
    int jb = 0, je = 0;
    if (kend > 0) {
        int C = (((kend + SPLITS - 1) / SPLITS) + 63) & ~63;
        jb = s * C;
        je = (jb + C < kend) ? (jb + C) : kend;
    }
    if (jb >= je) {
        float4 zz = make_float4(0.f, 0.f, 0.f, 0.f);
        *(float4*)&po[t8 * 4]      = zz;
        *(float4*)&po[32 + t8 * 4] = zz;
        if (t8 == 0) { g_pm[pidx] = -1e30f; g_pl[pidx] = 0.f; }
        return;
    }

    __shared__ __align__(16) float Ks[64][68];
    __shared__ __align__(16) float Vs[64][68];
    __shared__ float Ps[16][72];

    // Q row as 16 packed-pair vectors (64 floats)
    const size_t obase = ((size_t)b * NT + q) * NH;
    ulonglong2 qv[16];
    #pragma unroll
    for (int i = 0; i < 16; i++)
        qv[i] = *(const ulonglong2*)&g_q[obase + i * 4];

    float m = -1e30f, l = 0.f;
    ull oA0 = 0ull, oA1 = 0ull, oB0 = 0ull, oB1 = 0ull;

    for (int j0 = jb; j0 < je; j0 += 64) {
        __syncthreads();
        #pragma unroll
        for (int i = 0; i < 8; i++) {
            int idx4 = tid + 128 * i;
            int r    = idx4 >> 4;
            int c4   = (idx4 & 15) * 4;
            size_t g = ((size_t)b * NT + j0 + r) * NH + c4;
            *(float4*)&Ks[r][c4] = *(const float4*)&g_k[g];
            *(float4*)&Vs[r][c4] = *(const float4*)&g_v[g];
        }
        __syncthreads();

        // S = q . k for 8 strided keys
        float sv[8];
        #pragma unroll
        for (int j = 0; j < 8; j++) {
            const int kk  = t8 + 8 * j;
            const int key = j0 + kk;
            ull accA = 0ull, accB = 0ull;
            #pragma unroll
            for (int h4 = 0; h4 < 16; h4++) {
                ulonglong2 kv = *(const ulonglong2*)&Ks[kk][h4 * 4];
                fma2(accA, qv[h4].x, kv.x);
                fma2(accB, qv[h4].y, kv.y);
            }
            float2 ra = unpack2(accA), rb = unpack2(accB);
            float sc = (ra.x + ra.y) + (rb.x + rb.y);
            bool valid = (key <= q) && (key < L);
            sv[j] = valid ? sc * 0.125f : -1e30f;
        }

        float tm = sv[0];
        #pragma unroll
        for (int j = 1; j < 8; j++) tm = fmaxf(tm, sv[j]);
        #pragma unroll
        for (int off = 1; off < 8; off <<= 1)
            tm = fmaxf(tm, __shfl_xor_sync(0xffffffffu, tm, off));

        const float mn   = fmaxf(m, tm);
        const float corr = __expf(m - mn);

        float psum = 0.f;
        float pj[8];
        #pragma unroll
        for (int j = 0; j < 8; j++) {
            pj[j] = (sv[j] > -1e29f) ? __expf(sv[j] - mn) : 0.f;
            psum += pj[j];
        }
        #pragma unroll
        for (int off = 1; off < 8; off <<= 1)
            psum += __shfl_xor_sync(0xffffffffu, psum, off);

        l = l * corr + psum;
        m = mn;
        const ull c2 = pack2s(corr);
        mul2(oA0, c2); mul2(oA1, c2); mul2(oB0, c2); mul2(oB1, c2);

        #pragma unroll
        for (int j = 0; j < 8; j++) Ps[row][t8 + 8 * j] = pj[j];
        __syncthreads();

        #pragma unroll 4
        for (int kk = 0; kk < 64; kk++) {
            const ull pp = pack2s(Ps[row][kk]);
            ulonglong2 v0 = *(const ulonglong2*)&Vs[kk][t8 * 4];
            ulonglong2 v1 = *(const ulonglong2*)&Vs[kk][32 + t8 * 4];
            fma2(oA0, pp, v0.x);
            fma2(oA1, pp, v0.y);
            fma2(oB0, pp, v1.x);
            fma2(oB1, pp, v1.y);
        }
    }

    ulonglong2 stA; stA.x = oA0; stA.y = oA1;
    ulonglong2 stB; stB.x = oB0; stB.y = oB1;
    *(ulonglong2*)&po[t8 * 4]      = stA;
    *(ulonglong2*)&po[32 + t8 * 4] = stB;
    if (t8 == 0) { g_pm[pidx] = m; g_pl[pidx] = l; }
}

// ---------------------------------------------------------------------------
// Combine split-K partials: out = (sum_s o_s * e^{m_s - m*}) / (sum_s l_s e^{...})
// Rows with q >= L (or no valid key) output zero.
// ---------------------------------------------------------------------------
__global__ __launch_bounds__(128) void attn_combine(
    const int* __restrict__ valid_lens, float* __restrict__ out)
{
    const int b  = blockIdx.y;
    const int qt = blockIdx.x;
    const int tid = threadIdx.x;
    const int row = tid >> 3;
    const int t8  = tid & 7;
    const int q   = qt * 16 + row;
    int L = valid_lens[b];
    if (L < 0) L = 0;
    if (L > NT) L = NT;

    const size_t base0 = (((size_t)b * NQT + qt) * SPLITS) * 16 + row;

    float ms[SPLITS];
    float mstar = -1e30f;
    #pragma unroll
    for (int s = 0; s < SPLITS; s++) {
        ms[s] = g_pm[base0 + (size_t)s * 16];
        mstar = fmaxf(mstar, ms[s]);
    }

    float l = 0.f;
    float4 oA = make_float4(0.f, 0.f, 0.f, 0.f);
    float4 oB = make_float4(0.f, 0.f, 0.f, 0.f);
    #pragma unroll
    for (int s = 0; s < SPLITS; s++) {
        const float w = (ms[s] > -1e29f) ? __expf(ms[s] - mstar) : 0.f;
        const size_t pi = base0 + (size_t)s * 16;
        l += g_pl[pi] * w;
        float4 a = *(const float4*)&g_po[pi * NH + t8 * 4];
        float4 c = *(const float4*)&g_po[pi * NH + 32 + t8 * 4];
        oA.x += a.x * w; oA.y += a.y * w; oA.z += a.z * w; oA.w += a.w * w;
        oB.x += c.x * w; oB.y += c.y * w; oB.z += c.z * w; oB.w += c.w * w;
    }

    const float inv = (q < L && l > 0.f) ? (1.f / l) : 0.f;
    const size_t obase = ((size_t)b * NT + q) * NH;
    *(float4*)&out[obase + t8 * 4] =
        make_float4(oA.x * inv, oA.y * inv, oA.z * inv, oA.w * inv);
    *(float4*)&out[obase + 32 + t8 * 4] =
        make_float4(oB.x * inv, oB.y * inv, oB.z * inv, oB.w * inv);
}

extern "C" void kernel_launch(void* const* d_in, const int* in_sizes, int n_in,
                              void* d_out, int out_size)
{
    const float* x  = (const float*)d_in[0];
    const float* Wq = (const float*)d_in[1];
    const float* Wk = (const float*)d_in[2];
    const float* Wv = (const float*)d_in[3];
    const int*   vl = (const int*)d_in[4];
    float* out = (float*)d_out;

    proj_kernel<<<dim3(NT / 64, NB, 3), 256>>>(x, Wq, Wk, Wv, vl);
    attn_part<<<dim3(NQT, NB, SPLITS), 128>>>(vl);
    attn_combine<<<dim3(NQT, NB), 128>>>(vl, out);
}